// round 10
// baseline (speedup 1.0000x reference)
#include <cuda_runtime.h>
#include <cuda_fp16.h>
#include <cstdint>

#define NPTS 16384
#define BATCH 16
#define INC 7
typedef unsigned long long u64;
typedef unsigned int u32;

// ---------------- scratch ----------------
// point-major, k-pair packed: row (b,i) = 64 u32, u32 = half2(val[2kp], val[2kp+1])
__device__ u32                g_hhi[(size_t)BATCH * NPTS * 64];
__device__ u32                g_hlo[(size_t)BATCH * NPTS * 64];
__device__ u32                g_wphi[1024 * 64];                // (c, kp) of 64*W
__device__ u32                g_wplo[1024 * 64];
__device__ unsigned char      g_gid[BATCH * NPTS];
__device__ unsigned long long g_pmax[BATCH * 1024];  // (valbits<<32)|(~idx)
__device__ unsigned int       g_gmax[4 * 1024];
__device__ float              g_u1[17 * 512];

__device__ __forceinline__ void split_limbs(float v, unsigned short& hi, unsigned short& lo) {
    __half h = __float2half_rn(v);
    float r = v - __half2float(h);
    __half l = __float2half_rn(r);
    hi = __half_as_ushort(h);
    lo = __half_as_ushort(l);
}
__device__ __forceinline__ void mma16(float* d, const u32* a, const u32* b) {
    asm volatile("mma.sync.aligned.m16n8k16.row.col.f32.f16.f16.f32 "
                 "{%0,%1,%2,%3}, {%4,%5,%6,%7}, {%8,%9}, {%0,%1,%2,%3};"
                 : "+f"(d[0]), "+f"(d[1]), "+f"(d[2]), "+f"(d[3])
                 : "r"(a[0]), "r"(a[1]), "r"(a[2]), "r"(a[3]), "r"(b[0]), "r"(b[1]));
}
#define LDSM4(R, A) \
    asm volatile("ldmatrix.sync.aligned.m8n8.x4.shared.b16 {%0,%1,%2,%3}, [%4];" \
                 : "=r"((R)[0]), "=r"((R)[1]), "=r"((R)[2]), "=r"((R)[3]) : "r"(A))
__device__ __forceinline__ u32 smem_u32(const void* p) {
    u32 a; asm("{ .reg .u64 t; cvta.to.shared.u64 t, %1; cvt.u32.u64 %0, t; }" : "=r"(a) : "l"(p)); return a;
}
#define CP_ASYNC16(dst, src) asm volatile("cp.async.cg.shared.global [%0], [%1], 16;" :: "r"(dst), "l"(src) : "memory")
#define CP_COMMIT()  asm volatile("cp.async.commit_group;" ::: "memory")
#define CP_WAIT0()   asm volatile("cp.async.wait_group 0;" ::: "memory")
#define CP_WAIT1()   asm volatile("cp.async.wait_group 1;" ::: "memory")

// ---------------- kernel A: fused 7->64->64->64->128 + point-major plane output ----------------
#define KA_SMEM_FLOATS 24704

__device__ __forceinline__ void smcpy128(float* dst, const float* src, int n, int tid) {
    for (int i = tid; i < n; i += 128) dst[i] = src[i];
}
__device__ __forceinline__ void mlp64s(const float* __restrict__ sw, const float* __restrict__ sb,
                                       const float* __restrict__ ain, float* __restrict__ aout, int tid) {
#pragma unroll 1
    for (int c0 = 0; c0 < 64; c0 += 8) {
        float acc[8];
#pragma unroll
        for (int u = 0; u < 8; u++) acc[u] = sb[c0 + u];
#pragma unroll 4
        for (int k = 0; k < 64; k += 4) {
            float a0 = ain[(k + 0) * 128 + tid];
            float a1 = ain[(k + 1) * 128 + tid];
            float a2 = ain[(k + 2) * 128 + tid];
            float a3 = ain[(k + 3) * 128 + tid];
#pragma unroll
            for (int u = 0; u < 8; u++) {
                float4 w4 = *reinterpret_cast<const float4*>(&sw[(c0 + u) * 64 + k]);
                acc[u] = fmaf(w4.x, a0, acc[u]);
                acc[u] = fmaf(w4.y, a1, acc[u]);
                acc[u] = fmaf(w4.z, a2, acc[u]);
                acc[u] = fmaf(w4.w, a3, acc[u]);
            }
        }
#pragma unroll
        for (int u = 0; u < 8; u++) aout[(c0 + u) * 128 + tid] = fmaxf(acc[u], 0.0f);
    }
}

__global__ __launch_bounds__(128, 2)
void kA(const float* __restrict__ points,
        const float* __restrict__ wl0, const float* __restrict__ bl0,
        const float* __restrict__ wl1, const float* __restrict__ bl1,
        const float* __restrict__ wl2, const float* __restrict__ bl2,
        const float* __restrict__ wl3, const float* __restrict__ bl3) {
    extern __shared__ float sm[];
    float* wbuf = sm;
    float* hA = sm + 8320;
    float* hB = sm + 16512;
    const int tid = threadIdx.x;

    smcpy128(wbuf + 0,    wl0, 448,  tid);
    smcpy128(wbuf + 448,  bl0, 64,   tid);
    smcpy128(wbuf + 512,  wl1, 4096, tid);
    smcpy128(wbuf + 4608, bl1, 64,   tid);

    const int p = blockIdx.x * 128 + tid;
    const int b = p >> 14;
    const int i = p & (NPTS - 1);
    const float* pt = points + (size_t)b * INC * NPTS + i;
    float x[INC];
#pragma unroll
    for (int c = 0; c < INC; c++) x[c] = pt[(size_t)c * NPTS];

    int g = 0; float bv = x[3];
    if (x[4] > bv) { bv = x[4]; g = 1; }
    if (x[5] > bv) { bv = x[5]; g = 2; }
    if (x[6] > bv) { bv = x[6]; g = 3; }
    g_gid[p] = (unsigned char)g;

    __syncthreads();
#pragma unroll 1
    for (int c0 = 0; c0 < 64; c0 += 8) {
        float acc[8];
#pragma unroll
        for (int u = 0; u < 8; u++) {
            const float* wr = &wbuf[(c0 + u) * 7];
            float s = wbuf[448 + c0 + u];
#pragma unroll
            for (int k = 0; k < 7; k++) s = fmaf(wr[k], x[k], s);
            acc[u] = s;
        }
#pragma unroll
        for (int u = 0; u < 8; u++) hA[(c0 + u) * 128 + tid] = fmaxf(acc[u], 0.0f);
    }
    mlp64s(wbuf + 512, wbuf + 4608, hA, hB, tid);   // L1
    __syncthreads();

    smcpy128(wbuf + 0,    wl2, 4096, tid);
    smcpy128(wbuf + 4096, bl2, 64,   tid);
    __syncthreads();
    mlp64s(wbuf + 0, wbuf + 4096, hB, hA, tid);     // L2
    __syncthreads();

    smcpy128(wbuf + 0,    wl3, 8192, tid);
    smcpy128(wbuf + 8192, bl3, 128,  tid);
    __syncthreads();

    u32* ophi = g_hhi + (size_t)(b * NPTS + i) * 64;
    u32* oplo = g_hlo + (size_t)(b * NPTS + i) * 64;
#pragma unroll 1
    for (int c0 = 0; c0 < 128; c0 += 8) {
        float acc[8];
#pragma unroll
        for (int u = 0; u < 8; u++) acc[u] = wbuf[8192 + c0 + u];
#pragma unroll 4
        for (int k = 0; k < 64; k += 4) {
            float a0 = hA[(k + 0) * 128 + tid];
            float a1 = hA[(k + 1) * 128 + tid];
            float a2 = hA[(k + 2) * 128 + tid];
            float a3 = hA[(k + 3) * 128 + tid];
#pragma unroll
            for (int u = 0; u < 8; u++) {
                float4 w4 = *reinterpret_cast<const float4*>(&wbuf[(c0 + u) * 64 + k]);
                acc[u] = fmaf(w4.x, a0, acc[u]);
                acc[u] = fmaf(w4.y, a1, acc[u]);
                acc[u] = fmaf(w4.z, a2, acc[u]);
                acc[u] = fmaf(w4.w, a3, acc[u]);
            }
        }
        u32 vh[4], vl[4];
#pragma unroll
        for (int j = 0; j < 4; j++) {
            unsigned short h0, l0, h1, l1;
            split_limbs(fmaxf(acc[2 * j], 0.0f), h0, l0);
            split_limbs(fmaxf(acc[2 * j + 1], 0.0f), h1, l1);
            vh[j] = (u32)h0 | ((u32)h1 << 16);
            vl[j] = (u32)l0 | ((u32)l1 << 16);
        }
        *reinterpret_cast<uint4*>(ophi + c0 / 2) = make_uint4(vh[0], vh[1], vh[2], vh[3]);
        *reinterpret_cast<uint4*>(oplo + c0 / 2) = make_uint4(vl[0], vl[1], vl[2], vl[3]);
    }
}

// ---------------- kernel W: split 64*W into fp16 limb planes, k-pair packed ----------------
__global__ void kW(const float* __restrict__ wl4) {
    int t = blockIdx.x * blockDim.x + threadIdx.x;
    if (t >= 1024 * 64) return;
    int c = t >> 6, kp = t & 63;
    unsigned short h0, l0, h1, l1;
    split_limbs(wl4[c * 128 + 2 * kp] * 64.0f, h0, l0);
    split_limbs(wl4[c * 128 + 2 * kp + 1] * 64.0f, h1, l1);
    g_wphi[t] = (u32)h0 | ((u32)h1 << 16);
    g_wplo[t] = (u32)l0 | ((u32)l1 << 16);
}

// ---------------- kernel B: persistent 3-pass split-fp16 mma + ldmatrix fragments ----------------
#define PLW 68                        // row stride in u32 (272 B: 8 LDSM rows spread all 32 banks)
#define PLSZ (128 * PLW)              // one plane: 8704 u32
#define KB_W_U (2 * PLSZ)             // W: hi+lo planes
#define KB_H_U (2 * PLSZ)             // H buffer: hi+lo planes
#define KB_SMEM_BYTES ((KB_W_U + 2 * KB_H_U) * 4)   // 208896 B

__global__ __launch_bounds__(256, 1)
void kB(const float* __restrict__ bl4) {
    extern __shared__ float smf[];
    u32* swp = reinterpret_cast<u32*>(smf);
    u32* hbuf0 = swp + KB_W_U;
    u32* hbuf1 = hbuf0 + KB_H_U;
    __shared__ unsigned char gid_s[128];

    const int tid = threadIdx.x;
    const int bid = blockIdx.x;
    const int b  = bid >> 6;
    const int pg = (bid >> 3) & 7;
    const int cc = bid & 7;
    const int c0 = cc * 128;

    // W tile: [pl][c][kp] stride PLW
#pragma unroll
    for (int j = 0; j < 16; j++) {
        int idx = j * 256 + tid;                 // 4096 uint4 chunks
        int pl = idx >> 11, rem = idx & 2047;
        int r = rem >> 4, q = (rem & 15) * 4;
        const u32* src = (pl ? g_wplo : g_wphi) + (size_t)(c0 + r) * 64 + q;
        uint4 v = *reinterpret_cast<const uint4*>(src);
        *reinterpret_cast<uint4*>(&swp[pl * PLSZ + r * PLW + q]) = v;
    }

    const u32 swbase = smem_u32(swp);
    const u32 hadd[2] = { smem_u32(hbuf0), smem_u32(hbuf1) };

    // prefetch H tile 0: [pl][p][kp]
    {
        const int pbase = pg * 2048;
#pragma unroll
        for (int j = 0; j < 16; j++) {
            int idx = j * 256 + tid;
            int pl = idx >> 11, rem = idx & 2047;
            int row = rem >> 4, q = (rem & 15) * 4;
            const u32* src = (pl ? g_hlo : g_hhi) + (size_t)(b * NPTS + pbase + row) * 64 + q;
            CP_ASYNC16(hadd[0] + (u32)(pl * PLSZ + row * PLW + q) * 4, src);
        }
        CP_COMMIT();
    }

    const int lane = tid & 31, wrp = tid >> 5;
    const int mw = wrp >> 1;
    const int nw = wrp & 1;
    const int gid4 = lane >> 2, tig = lane & 3;
    const int cw = mw * 32, pw = nw * 64;

    // ldmatrix lane addresses (byte offsets); advance +32 B per k-step
    const int lm = lane >> 3, lr = lane & 7;
    u32 aadr[2][2];     // [pl][mt]
#pragma unroll
    for (int pl = 0; pl < 2; pl++)
#pragma unroll
        for (int mt = 0; mt < 2; mt++) {
            int row = cw + mt * 16 + lr + (lm & 1) * 8;
            int col = (lm >> 1) * 4;
            aadr[pl][mt] = swbase + (u32)(pl * PLSZ + row * PLW + col) * 4;
        }
    u32 boff[2][4];     // [pl][np] offsets within an H buffer
#pragma unroll
    for (int pl = 0; pl < 2; pl++)
#pragma unroll
        for (int np = 0; np < 4; np++) {
            int row = pw + np * 16 + lr + (lm >> 1) * 8;
            int col = (lm & 1) * 4;
            boff[pl][np] = (u32)(pl * PLSZ + row * PLW + col) * 4;
        }

#pragma unroll 1
    for (int t = 0; t < 16; t++) {
        const int pbase = (pg * 16 + t) * 128;
        u32* shp = (t & 1) ? hbuf1 : hbuf0;
        if (t + 1 < 16) {
            const int pn = (pg * 16 + t + 1) * 128;
            const u32 dsta = hadd[(t + 1) & 1];
#pragma unroll
            for (int j = 0; j < 16; j++) {
                int idx = j * 256 + tid;
                int pl = idx >> 11, rem = idx & 2047;
                int row = rem >> 4, q = (rem & 15) * 4;
                const u32* src = (pl ? g_hlo : g_hhi) + (size_t)(b * NPTS + pn + row) * 64 + q;
                CP_ASYNC16(dsta + (u32)(pl * PLSZ + row * PLW + q) * 4, src);
            }
            CP_COMMIT();
            CP_WAIT1();
        } else {
            CP_WAIT0();
        }
        if (tid < 128) gid_s[tid] = g_gid[b * NPTS + pbase + tid];
        __syncthreads();

        float acc[2][8][4];
#pragma unroll
        for (int mt = 0; mt < 2; mt++)
#pragma unroll
            for (int nt = 0; nt < 8; nt++)
#pragma unroll
                for (int j = 0; j < 4; j++) acc[mt][nt][j] = 0.0f;

        u32 aa[2][2] = { { aadr[0][0], aadr[0][1] }, { aadr[1][0], aadr[1][1] } };
        u32 ba[2][4];
#pragma unroll
        for (int pl = 0; pl < 2; pl++)
#pragma unroll
            for (int np = 0; np < 4; np++) ba[pl][np] = hadd[t & 1] + boff[pl][np];

#pragma unroll 1
        for (int kk = 0; kk < 8; kk++) {
            u32 af[2][2][4];     // [pl][mt][a0..a3]
#pragma unroll
            for (int pl = 0; pl < 2; pl++)
#pragma unroll
                for (int mt = 0; mt < 2; mt++) {
                    LDSM4(af[pl][mt], aa[pl][mt]);
                    aa[pl][mt] += 32;
                }
            u32 bf[2][4][4];     // [pl][np][b0(2np),b1(2np),b0(2np+1),b1(2np+1)]
#pragma unroll
            for (int pl = 0; pl < 2; pl++)
#pragma unroll
                for (int np = 0; np < 4; np++) {
                    LDSM4(bf[pl][np], ba[pl][np]);
                    ba[pl][np] += 32;
                }
#pragma unroll
            for (int mt = 0; mt < 2; mt++)
#pragma unroll
                for (int nt = 0; nt < 8; nt++) {
                    const u32* bhi = &bf[0][nt >> 1][(nt & 1) * 2];
                    const u32* blo = &bf[1][nt >> 1][(nt & 1) * 2];
                    mma16(acc[mt][nt], af[0][mt], bhi);
                    mma16(acc[mt][nt], af[0][mt], blo);
                    mma16(acc[mt][nt], af[1][mt], bhi);
                }
        }
        __syncthreads();   // all reads of shp done; reuse region for staging

        u64* skey = reinterpret_cast<u64*>(shp);             // 8 KB
        float* sg = reinterpret_cast<float*>(skey + 1024);   // 16 KB
        const int slot = nw * 4 + tig;
#pragma unroll
        for (int mt = 0; mt < 2; mt++)
#pragma unroll
            for (int hf = 0; hf < 2; hf++) {
                const int c = cw + mt * 16 + gid4 + hf * 8;
                const float bias_c = __ldg(&bl4[c0 + c]);
                u64 key = 0ull;
                float g0 = 0.f, g1 = 0.f, g2 = 0.f, g3 = 0.f;
#pragma unroll
                for (int nt = 0; nt < 8; nt++)
#pragma unroll
                    for (int jj = 0; jj < 2; jj++) {
                        float val = fmaxf(fmaf(acc[mt][nt][hf * 2 + jj], 0.015625f, bias_c), 0.0f);
                        const int pl = pw + nt * 8 + tig * 2 + jj;
                        u64 k = ((u64)__float_as_uint(val) << 32) |
                                (u64)(0xFFFFFFFFu - (u32)(pbase + pl));
                        if (k > key) key = k;
                        const int gi = gid_s[pl];
                        g0 = fmaxf(g0, gi == 0 ? val : 0.f);
                        g1 = fmaxf(g1, gi == 1 ? val : 0.f);
                        g2 = fmaxf(g2, gi == 2 ? val : 0.f);
                        g3 = fmaxf(g3, gi == 3 ? val : 0.f);
                    }
                skey[c * 8 + slot] = key;
                sg[(c * 8 + slot) * 4 + 0] = g0;
                sg[(c * 8 + slot) * 4 + 1] = g1;
                sg[(c * 8 + slot) * 4 + 2] = g2;
                sg[(c * 8 + slot) * 4 + 3] = g3;
            }
        __syncthreads();

        if (tid < 128) {
            const int c = tid;
            u64 m = skey[c * 8];
            float mg[4] = { sg[c * 32 + 0], sg[c * 32 + 1], sg[c * 32 + 2], sg[c * 32 + 3] };
#pragma unroll
            for (int q = 1; q < 8; q++) {
                u64 e = skey[c * 8 + q];
                if (e > m) m = e;
#pragma unroll
                for (int g = 0; g < 4; g++) mg[g] = fmaxf(mg[g], sg[(c * 8 + q) * 4 + g]);
            }
            atomicMax(&g_pmax[b * 1024 + c0 + c], m);
#pragma unroll
            for (int g = 0; g < 4; g++)
                atomicMax(&g_gmax[g * 1024 + c0 + c], __float_as_uint(mg[g]));
        }
        __syncthreads();   // staging reads done before buffer is prefetch-overwritten
    }
}

// ---------------- init + tail MLPs (unchanged) ----------------
__global__ void kInit() {
    int t = blockIdx.x * blockDim.x + threadIdx.x;
    if (t < BATCH * 1024) g_pmax[t] = 0ull;
    if (t < 4 * 1024) g_gmax[t] = 0u;
}

__global__ void kC1(const float* __restrict__ wg0, const float* __restrict__ bg0,
                    const float* __restrict__ wgr0, const float* __restrict__ bgr0,
                    float* __restrict__ out) {
    const int gtid = blockIdx.x * blockDim.x + threadIdx.x;
    if (gtid < BATCH * 1024) {
        unsigned long long pv = g_pmax[gtid];
        out[4096 + gtid] = (float)(0xFFFFFFFFu - (unsigned int)(pv & 0xFFFFFFFFull));
    }
    const int wid = gtid >> 5;
    const int lane = gtid & 31;
    const int row = wid >> 9;
    const int j = wid & 511;
    if (row > 16) return;
    float s = 0.0f;
    if (row < 16) {
        const float* wr = wg0 + (size_t)j * 1024;
        const unsigned long long* pbuf = g_pmax + row * 1024;
        for (int k = lane; k < 1024; k += 32)
            s = fmaf(wr[k], __uint_as_float((unsigned int)(pbuf[k] >> 32)), s);
    } else {
        const float* wr = wgr0 + (size_t)j * 4096;
        for (int k = lane; k < 4096; k += 32)
            s = fmaf(wr[k], __uint_as_float(g_gmax[k]), s);
    }
#pragma unroll
    for (int o = 16; o; o >>= 1) s += __shfl_xor_sync(0xFFFFFFFFu, s, o);
    if (lane == 0) {
        float bb = (row < 16) ? bg0[j] : bgr0[j];
        g_u1[row * 512 + j] = fmaxf(s + bb, 0.0f);
    }
}

__global__ void kC2(const float* __restrict__ wg1, const float* __restrict__ bg1,
                    const float* __restrict__ wgr1, const float* __restrict__ bgr1,
                    float* __restrict__ out) {
    const int gtid = blockIdx.x * blockDim.x + threadIdx.x;
    const int wid = gtid >> 5;
    const int lane = gtid & 31;
    const int row = wid >> 7;
    const int j = wid & 127;
    if (row > 16) return;
    const float* wr = ((row < 16) ? wg1 : wgr1) + (size_t)j * 512;
    const float* in = g_u1 + row * 512;
    float s = 0.0f;
    for (int k = lane; k < 512; k += 32) s = fmaf(wr[k], in[k], s);
#pragma unroll
    for (int o = 16; o; o >>= 1) s += __shfl_xor_sync(0xFFFFFFFFu, s, o);
    s = __shfl_sync(0xFFFFFFFFu, s, 0);
    float bb = (row < 16) ? bg1[j] : bgr1[j];
    float val = fmaxf(s + bb, 0.0f);
    if (row < 16) {
        if (lane == 0) out[row * 256 + 128 + j] = val;
    } else {
        if (lane < 16) out[lane * 256 + j] = val;
    }
}

// ---------------- launch ----------------
extern "C" void kernel_launch(void* const* d_in, const int* in_sizes, int n_in,
                              void* d_out, int out_size) {
    const float* points = (const float*)d_in[0];
    const float* wl0 = (const float*)d_in[1];  const float* bl0 = (const float*)d_in[2];
    const float* wl1 = (const float*)d_in[3];  const float* bl1 = (const float*)d_in[4];
    const float* wl2 = (const float*)d_in[5];  const float* bl2 = (const float*)d_in[6];
    const float* wl3 = (const float*)d_in[7];  const float* bl3 = (const float*)d_in[8];
    const float* wl4 = (const float*)d_in[9];  const float* bl4 = (const float*)d_in[10];
    const float* wg0 = (const float*)d_in[11]; const float* bg0 = (const float*)d_in[12];
    const float* wg1 = (const float*)d_in[13]; const float* bg1 = (const float*)d_in[14];
    const float* wgr0 = (const float*)d_in[15]; const float* bgr0 = (const float*)d_in[16];
    const float* wgr1 = (const float*)d_in[17]; const float* bgr1 = (const float*)d_in[18];
    float* out = (float*)d_out;

    cudaFuncSetAttribute(kA, cudaFuncAttributeMaxDynamicSharedMemorySize,
                         KA_SMEM_FLOATS * (int)sizeof(float));
    cudaFuncSetAttribute(kB, cudaFuncAttributeMaxDynamicSharedMemorySize, KB_SMEM_BYTES);

    kInit<<<64, 256>>>();
    kW<<<256, 256>>>(wl4);
    kA<<<(BATCH * NPTS) / 128, 128, KA_SMEM_FLOATS * sizeof(float)>>>(
        points, wl0, bl0, wl1, bl1, wl2, bl2, wl3, bl3);
    kB<<<1024, 256, KB_SMEM_BYTES>>>(bl4);
    kC1<<<1088, 256>>>(wg0, bg0, wgr0, bgr0, out);
    kC2<<<272, 256>>>(wg1, bg1, wgr1, bgr1, out);
}